// round 1
// baseline (speedup 1.0000x reference)
#include <cuda_runtime.h>
#include <cuda_bf16.h>
#include <cstdint>

// Problem constants (validated against in_sizes at launch)
#define MAX_N 50000
#define MAX_E 800000
#define D 128

// ------------------------- scratch (device globals; no allocation) ----------
__device__ float g_agg1[(size_t)MAX_N * D];   // layer-1 neighbor sums
__device__ float g_cnt[MAX_N];                // in-degree counts
__device__ float g_inv[MAX_N];                // 1/max(cnt,1)
__device__ float g_h[(size_t)MAX_N * D];      // layer-1 activations
__device__ float g_z[(size_t)MAX_N * 2];      // h @ W2_l^T   (pre-aggregation)
__device__ float g_s[(size_t)MAX_N * 2];      // h @ W2_r^T + b2 (self term)
__device__ float g_agg2[(size_t)MAX_N * 2];   // layer-2 aggregated z
__device__ int   g_is64;                      // edge_index dtype flag

// ------------------------- helpers ------------------------------------------
__device__ __forceinline__ long long load_idx(const void* ei, long long i) {
    if (g_is64) return ((const long long*)ei)[i];
    return (long long)((const int*)ei)[i];
}

// Detect whether edge_index is int64 or int32.
// int64 values < 50000 => every odd 32-bit word (high half) is 0.
// int32 => odd words are random indices; P(all 64 zero) ~ 0.
__global__ void detect_kernel(const void* ei) {
    const unsigned* u = (const unsigned*)ei;
    int ok = 1;
    for (int i = 0; i < 64; i++) {
        if (u[2 * i + 1] != 0u) { ok = 0; break; }
    }
    g_is64 = ok;
}

// Zero all accumulators (agg1, cnt, agg2) in one grid-stride kernel.
__global__ void zero_kernel(int n_nodes) {
    long long n_agg1 = (long long)n_nodes * D / 4;   // float4 count
    long long n_cnt  = n_nodes;                       // floats
    long long n_agg2 = (long long)n_nodes * 2;        // floats
    long long total  = n_agg1 + n_cnt + n_agg2;
    float4 z4 = make_float4(0.f, 0.f, 0.f, 0.f);
    for (long long i = (long long)blockIdx.x * blockDim.x + threadIdx.x;
         i < total; i += (long long)gridDim.x * blockDim.x) {
        if (i < n_agg1) {
            ((float4*)g_agg1)[i] = z4;
        } else if (i < n_agg1 + n_cnt) {
            g_cnt[i - n_agg1] = 0.f;
        } else {
            g_agg2[i - n_agg1 - n_cnt] = 0.f;
        }
    }
}

// ---------------- layer-1 aggregation: warp per edge, red.v4 ---------------
__global__ void agg1_kernel(const float* __restrict__ x, const void* __restrict__ ei,
                            long long E) {
    long long gw = ((long long)blockIdx.x * blockDim.x + threadIdx.x) >> 5;
    int lane = threadIdx.x & 31;
    if (gw >= E) return;
    long long s = load_idx(ei, gw);
    long long d = load_idx(ei, E + gw);
    float4 v = *(const float4*)(x + s * D + lane * 4);
    float* dst = g_agg1 + d * D + lane * 4;
    asm volatile("red.global.add.v4.f32 [%0], {%1, %2, %3, %4};"
                 :: "l"(dst), "f"(v.x), "f"(v.y), "f"(v.z), "f"(v.w)
                 : "memory");
    if (lane == 0) atomicAdd(g_cnt + d, 1.0f);
}

// ---------------- inverse counts --------------------------------------------
__global__ void inv_kernel(int n) {
    int i = blockIdx.x * blockDim.x + threadIdx.x;
    if (i < n) g_inv[i] = 1.0f / fmaxf(g_cnt[i], 1.0f);
}

// ---------------- layer-1 fused GEMM: h = relu([agg*inv, x] @ Wcat^T + b1) --
// M x 128 output, K = 256 (first 128 from normalized agg w/ W1_l, rest x w/ W1_r)
#define BM 128
#define BN 128
#define BK 16
#define TM 8
#define TN 8
__global__ __launch_bounds__(256, 2)
void gemm1_kernel(const float* __restrict__ x,
                  const float* __restrict__ W1l, const float* __restrict__ W1r,
                  const float* __restrict__ b1, int M) {
    __shared__ float As[BK][BM];
    __shared__ float Bs[BK][BN];
    int block_row = blockIdx.x * BM;
    int tid = threadIdx.x;
    int tx = tid & 15;        // 16 col-groups * 8 = 128 cols
    int ty = tid >> 4;        // 16 row-groups * 8 = 128 rows
    float acc[TM][TN];
    #pragma unroll
    for (int i = 0; i < TM; i++)
        #pragma unroll
        for (int j = 0; j < TN; j++) acc[i][j] = 0.f;

    #pragma unroll 1
    for (int kt = 0; kt < 2 * D; kt += BK) {
        bool isAgg = (kt < D);
        int kk0 = isAgg ? kt : kt - D;
        const float* Aptr = isAgg ? g_agg1 : x;
        const float* Wptr = isAgg ? W1l : W1r;

        // Load A tile (BM x BK), store transposed As[k][m]
        #pragma unroll
        for (int p = 0; p < 2; p++) {
            int f = tid + p * 256;
            int r = f >> 2;
            int c4 = (f & 3) * 4;
            int grow = block_row + r;
            float4 v = make_float4(0.f, 0.f, 0.f, 0.f);
            if (grow < M) {
                v = *(const float4*)(Aptr + (size_t)grow * D + kk0 + c4);
                if (isAgg) {
                    float sc = g_inv[grow];
                    v.x *= sc; v.y *= sc; v.z *= sc; v.w *= sc;
                }
            }
            As[c4 + 0][r] = v.x; As[c4 + 1][r] = v.y;
            As[c4 + 2][r] = v.z; As[c4 + 3][r] = v.w;
        }
        // Load B tile: Bs[k][j] = W[j][kk0+k]
        #pragma unroll
        for (int p = 0; p < 2; p++) {
            int f = tid + p * 256;
            int j = f >> 2;
            int c4 = (f & 3) * 4;
            float4 v = *(const float4*)(Wptr + (size_t)j * D + kk0 + c4);
            Bs[c4 + 0][j] = v.x; Bs[c4 + 1][j] = v.y;
            Bs[c4 + 2][j] = v.z; Bs[c4 + 3][j] = v.w;
        }
        __syncthreads();

        #pragma unroll
        for (int k = 0; k < BK; k++) {
            float4 a0 = *(const float4*)&As[k][ty * TM + 0];
            float4 a1 = *(const float4*)&As[k][ty * TM + 4];
            float4 b0 = *(const float4*)&Bs[k][tx * TN + 0];
            float4 b1v = *(const float4*)&Bs[k][tx * TN + 4];
            float a[TM] = {a0.x, a0.y, a0.z, a0.w, a1.x, a1.y, a1.z, a1.w};
            float b[TN] = {b0.x, b0.y, b0.z, b0.w, b1v.x, b1v.y, b1v.z, b1v.w};
            #pragma unroll
            for (int i = 0; i < TM; i++)
                #pragma unroll
                for (int j = 0; j < TN; j++)
                    acc[i][j] += a[i] * b[j];
        }
        __syncthreads();
    }

    // Epilogue: + bias, relu, store h
    #pragma unroll
    for (int i = 0; i < TM; i++) {
        int grow = block_row + ty * TM + i;
        if (grow >= M) break;
        #pragma unroll
        for (int j = 0; j < TN; j += 4) {
            int col = tx * TN + j;
            float4 bb = *(const float4*)(b1 + col);
            float4 v;
            v.x = fmaxf(acc[i][j + 0] + bb.x, 0.f);
            v.y = fmaxf(acc[i][j + 1] + bb.y, 0.f);
            v.z = fmaxf(acc[i][j + 2] + bb.z, 0.f);
            v.w = fmaxf(acc[i][j + 3] + bb.w, 0.f);
            *(float4*)(g_h + (size_t)grow * D + col) = v;
        }
    }
}

// ---------------- layer-2 projections: z = h@W2l^T, s = h@W2r^T + b2 --------
__global__ void zs_kernel(const float* __restrict__ W2l, const float* __restrict__ W2r,
                          const float* __restrict__ b2, int M) {
    long long row = ((long long)blockIdx.x * blockDim.x + threadIdx.x) >> 5;
    int lane = threadIdx.x & 31;
    if (row >= M) return;
    float4 hv = *(const float4*)(g_h + row * D + lane * 4);
    float4 wl0 = *(const float4*)(W2l + lane * 4);
    float4 wl1 = *(const float4*)(W2l + D + lane * 4);
    float4 wr0 = *(const float4*)(W2r + lane * 4);
    float4 wr1 = *(const float4*)(W2r + D + lane * 4);
    float d0 = hv.x * wl0.x + hv.y * wl0.y + hv.z * wl0.z + hv.w * wl0.w;
    float d1 = hv.x * wl1.x + hv.y * wl1.y + hv.z * wl1.z + hv.w * wl1.w;
    float d2 = hv.x * wr0.x + hv.y * wr0.y + hv.z * wr0.z + hv.w * wr0.w;
    float d3 = hv.x * wr1.x + hv.y * wr1.y + hv.z * wr1.z + hv.w * wr1.w;
    #pragma unroll
    for (int o = 16; o; o >>= 1) {
        d0 += __shfl_xor_sync(0xffffffffu, d0, o);
        d1 += __shfl_xor_sync(0xffffffffu, d1, o);
        d2 += __shfl_xor_sync(0xffffffffu, d2, o);
        d3 += __shfl_xor_sync(0xffffffffu, d3, o);
    }
    if (lane == 0) {
        g_z[row * 2 + 0] = d0;
        g_z[row * 2 + 1] = d1;
        g_s[row * 2 + 0] = d2 + b2[0];
        g_s[row * 2 + 1] = d3 + b2[1];
    }
}

// ---------------- layer-2 aggregation: thread per edge, red.v2 --------------
__global__ void agg2_kernel(const void* __restrict__ ei, long long E) {
    long long e = (long long)blockIdx.x * blockDim.x + threadIdx.x;
    if (e >= E) return;
    long long s = load_idx(ei, e);
    long long d = load_idx(ei, E + e);
    float2 v = *(const float2*)(g_z + s * 2);
    float* dst = g_agg2 + d * 2;
    asm volatile("red.global.add.v2.f32 [%0], {%1, %2};"
                 :: "l"(dst), "f"(v.x), "f"(v.y)
                 : "memory");
}

// ---------------- final: out = agg2 * inv + s -------------------------------
__global__ void final_kernel(float* __restrict__ out, int M) {
    int i = blockIdx.x * blockDim.x + threadIdx.x;
    if (i >= M) return;
    float inv = g_inv[i];
    float2 a = *(const float2*)(g_agg2 + (size_t)i * 2);
    float2 s = *(const float2*)(g_s + (size_t)i * 2);
    float2 o;
    o.x = a.x * inv + s.x;
    o.y = a.y * inv + s.y;
    *(float2*)(out + (size_t)i * 2) = o;
}

// ------------------------- launch -------------------------------------------
extern "C" void kernel_launch(void* const* d_in, const int* in_sizes, int n_in,
                              void* d_out, int out_size) {
    const float* x   = (const float*)d_in[0];
    const void*  ei  = d_in[1];               // int64 or int32, detected on device
    const float* W1l = (const float*)d_in[2];
    const float* W1r = (const float*)d_in[3];
    const float* b1  = (const float*)d_in[4];
    const float* W2l = (const float*)d_in[5];
    const float* W2r = (const float*)d_in[6];
    const float* b2  = (const float*)d_in[7];
    float* out = (float*)d_out;

    int M = in_sizes[0] / D;            // 50000 nodes
    long long E = in_sizes[1] / 2;      // 800000 edges

    detect_kernel<<<1, 1>>>(ei);

    {
        long long total = (long long)M * D / 4 + M + (long long)M * 2;
        int blocks = (int)((total + 255) / 256);
        if (blocks > 4096) blocks = 4096;
        zero_kernel<<<blocks, 256>>>(M);
    }

    {
        long long threads = E * 32;
        int blocks = (int)((threads + 255) / 256);
        agg1_kernel<<<blocks, 256>>>(x, ei, E);
    }

    inv_kernel<<<(M + 255) / 256, 256>>>(M);

    gemm1_kernel<<<(M + BM - 1) / BM, 256>>>(x, W1l, W1r, b1, M);

    {
        long long threads = (long long)M * 32;
        int blocks = (int)((threads + 255) / 256);
        zs_kernel<<<blocks, 256>>>(W2l, W2r, b2, M);
    }

    agg2_kernel<<<(int)((E + 255) / 256), 256>>>(ei, E);

    final_kernel<<<(M + 255) / 256, 256>>>(out, M);
}